// round 9
// baseline (speedup 1.0000x reference)
#include <cuda_runtime.h>
#include <cuda_bf16.h>
#include <mma.h>
#include <math_constants.h>
#include <cstdint>

using namespace nvcuda;

#define DMODEL 1024
#define NHEADS 16
#define DHEAD  64
#define NBATCH 2
#define SQ     2048
#define SK     2048
#define MROWS  (NBATCH * SQ)   // 4096

// ---------------------------------------------------------------------------
// Scratch (device globals: no allocation allowed)
// ---------------------------------------------------------------------------
__device__ float g_qh[(size_t)NBATCH * NHEADS * SQ * DHEAD];   // [b,h,q,d] tf32 bits
__device__ float g_kh[(size_t)NBATCH * NHEADS * SK * DHEAD];   // tf32 bits
__device__ float g_vh[(size_t)NBATCH * NHEADS * SK * DHEAD];   // tf32 bits
__device__ float g_attn[(size_t)NBATCH * SQ * DMODEL];          // [b,q,h*64+d] tf32 bits
__device__ float g_act[(size_t)3 * MROWS * DMODEL];             // tf32(q,k,v)
__device__ float g_w[(size_t)3 * DMODEL * DMODEL];              // tf32(Wq,Wk,Wv)
__device__ float g_wo[(size_t)DMODEL * DMODEL];                 // tf32(Wo)

// ---------------------------------------------------------------------------
// helpers
// ---------------------------------------------------------------------------
__device__ __forceinline__ void cp_async16(void* smem, const void* gmem) {
    uint32_t s = (uint32_t)__cvta_generic_to_shared(smem);
    asm volatile("cp.async.cg.shared.global [%0], [%1], 16;\n" :: "r"(s), "l"(gmem));
}
__device__ __forceinline__ void cp_commit() { asm volatile("cp.async.commit_group;\n"); }
template<int N> __device__ __forceinline__ void cp_wait() {
    asm volatile("cp.async.wait_group %0;\n" :: "n"(N));
}
__device__ __forceinline__ uint32_t f2tf32(float f) {
    uint32_t r; asm("cvt.rna.tf32.f32 %0, %1;" : "=r"(r) : "f"(f)); return r;
}
__device__ __forceinline__ void mma_tf32(float c[4], const uint32_t a[4], uint32_t b0, uint32_t b1) {
    asm volatile("mma.sync.aligned.m16n8k8.row.col.f32.tf32.tf32.f32 "
        "{%0,%1,%2,%3}, {%4,%5,%6,%7}, {%8,%9}, {%0,%1,%2,%3};\n"
        : "+f"(c[0]), "+f"(c[1]), "+f"(c[2]), "+f"(c[3])
        : "r"(a[0]), "r"(a[1]), "r"(a[2]), "r"(a[3]), "r"(b0), "r"(b1));
}

// ---------------------------------------------------------------------------
// Preconvert: round inputs + weights to tf32 bits once.
// grid (4096, 7): y=0..2 -> q,k,v; y=3..6 -> Wq,Wk,Wv,Wo
// ---------------------------------------------------------------------------
__global__ __launch_bounds__(256)
void preconvert_kernel(const float4* __restrict__ q, const float4* __restrict__ k,
                       const float4* __restrict__ v, const float4* __restrict__ wq,
                       const float4* __restrict__ wk, const float4* __restrict__ wv,
                       const float4* __restrict__ wo)
{
    const int y = blockIdx.y;
    const float4* src;
    float4* dst;
    int n4;
    if (y < 3) {
        src = (y == 0) ? q : (y == 1) ? k : v;
        dst = (float4*)g_act + (size_t)y * (MROWS * DMODEL / 4);
        n4 = MROWS * DMODEL / 4;
    } else {
        src = (y == 3) ? wq : (y == 4) ? wk : (y == 5) ? wv : wo;
        dst = (y < 6) ? (float4*)g_w + (size_t)(y - 3) * (DMODEL * DMODEL / 4)
                      : (float4*)g_wo;
        n4 = DMODEL * DMODEL / 4;
    }
    int idx = blockIdx.x * 256 + threadIdx.x;
    if (idx < n4) {
        float4 s = src[idx];
        uint4 u;
        u.x = f2tf32(s.x); u.y = f2tf32(s.y);
        u.z = f2tf32(s.z); u.w = f2tf32(s.w);
        ((uint4*)dst)[idx] = u;
    }
}

// ---------------------------------------------------------------------------
// TF32 GEMM v5: CTA 128x128, 4 warps, warp tile 64x64, BK=32, cp.async double
// buffering. R6 inner loop (all 4 b-frags live). Epilogue staging reuses the
// dynamic smem A-buffer (no static smem), so 3 CTAs/SM fit:
//   3 x (70656 dyn + 1024 reserved) = 215 KB < 228 KB, 3 x 128 x 168 regs <= RF.
// MODE 0: batched projections, grid.z selects (g_act slice, g_w slice, bias_z)
//         -> head-major g_qh/g_kh/g_vh, epilogue rounds to tf32 bits.
// MODE 1: out = g_attn @ g_wo + bo, plain fp32 row-major.
// ---------------------------------------------------------------------------
#define G_ALD 36
#define G_BLD 132
#define G_ASZ (128 * G_ALD)
#define G_BSZ (32 * G_BLD)
#define GEMM_SMEM ((2 * G_ASZ + 2 * G_BSZ) * (int)sizeof(float))  // 70656

template<int MODE>
__global__ __launch_bounds__(128, 3)
void gemm_tf32_kernel(const float* __restrict__ bias0,
                      const float* __restrict__ bias1,
                      const float* __restrict__ bias2,
                      float* __restrict__ out)
{
    extern __shared__ float gsm[];
    float* Asm = gsm;                   // [2][128][36]
    float* Bsm = gsm + 2 * G_ASZ;       // [2][32][132]

    const int z = blockIdx.z;
    const float* Ap   = (MODE == 1) ? g_attn : g_act + (size_t)z * (MROWS * DMODEL);
    const float* W    = (MODE == 1) ? g_wo   : g_w   + (size_t)z * (DMODEL * DMODEL);
    const float* bias = (MODE == 1) ? bias0  : (z == 0) ? bias0 : (z == 1) ? bias1 : bias2;

    const int tid    = threadIdx.x;
    const int wid    = tid >> 5;
    const int lane   = tid & 31;
    const int warp_m = wid >> 1;
    const int warp_n = wid & 1;
    const int m0 = blockIdx.y * 128;
    const int n0 = blockIdx.x * 128;

    wmma::fragment<wmma::accumulator, 16, 16, 8, float> acc[4][4];
#pragma unroll
    for (int i = 0; i < 4; i++)
#pragma unroll
        for (int j = 0; j < 4; j++)
            wmma::fill_fragment(acc[i][j], 0.0f);

#define GEMM_PREFETCH(IT, BUF)                                                      \
    {                                                                               \
        int k0 = (IT) * 32;                                                         \
        _Pragma("unroll")                                                           \
        for (int i = 0; i < 8; i++) {                                               \
            int idx = tid + i * 128;                                                \
            int r = idx >> 3, c4 = idx & 7;                                         \
            cp_async16(&Asm[(BUF) * G_ASZ + r * G_ALD + c4 * 4],                    \
                       Ap + (size_t)(m0 + r) * DMODEL + k0 + c4 * 4);               \
        }                                                                           \
        _Pragma("unroll")                                                           \
        for (int i = 0; i < 8; i++) {                                               \
            int idx = tid + i * 128;                                                \
            int r = idx >> 5, c4 = idx & 31;                                        \
            cp_async16(&Bsm[(BUF) * G_BSZ + r * G_BLD + c4 * 4],                    \
                       W + (size_t)(k0 + r) * DMODEL + n0 + c4 * 4);                \
        }                                                                           \
        cp_commit();                                                                \
    }

    GEMM_PREFETCH(0, 0);
    GEMM_PREFETCH(1, 1);

    for (int it = 0; it < 32; it++) {
        if (it + 1 < 32) cp_wait<1>(); else cp_wait<0>();
        __syncthreads();

        const int buf = it & 1;
        const float* Asb = Asm + buf * G_ASZ;
        const float* Bsb = Bsm + buf * G_BSZ;

#pragma unroll
        for (int kf = 0; kf < 4; kf++) {
            wmma::fragment<wmma::matrix_a, 16, 16, 8, wmma::precision::tf32, wmma::row_major> a[4];
            wmma::fragment<wmma::matrix_b, 16, 16, 8, wmma::precision::tf32, wmma::row_major> b[4];
#pragma unroll
            for (int i = 0; i < 4; i++)
                wmma::load_matrix_sync(a[i], Asb + (warp_m * 64 + i * 16) * G_ALD + kf * 8, G_ALD);
#pragma unroll
            for (int j = 0; j < 4; j++)
                wmma::load_matrix_sync(b[j], Bsb + (kf * 8) * G_BLD + warp_n * 64 + j * 16, G_BLD);
#pragma unroll
            for (int i = 0; i < 4; i++)
#pragma unroll
                for (int j = 0; j < 4; j++)
                    wmma::mma_sync(acc[i][j], a[i], b[j], acc[i][j]);
        }
        __syncthreads();
        if (it + 2 < 32) GEMM_PREFETCH(it + 2, buf);
    }
#undef GEMM_PREFETCH

    // Epilogue: per-warp 1KB staging slice carved from the (now idle) smem.
    // All warps are past the final __syncthreads; each slice is warp-private.
    float* stage = gsm + wid * 256;
#pragma unroll
    for (int i = 0; i < 4; i++) {
#pragma unroll
        for (int j = 0; j < 4; j++) {
            wmma::store_matrix_sync(stage, acc[i][j], 16, wmma::mem_row_major);
            __syncwarp();
            int grow0 = m0 + warp_m * 64 + i * 16;
            int gcol0 = n0 + warp_n * 64 + j * 16;
#pragma unroll
            for (int t = lane; t < 256; t += 32) {
                int r = t >> 4, c = t & 15;
                int grow = grow0 + r;
                int gcol = gcol0 + c;
                float v = stage[t] + bias[gcol];
                if (MODE == 0) {
                    int b_ = grow >> 11;
                    int qr = grow & 2047;
                    int h_ = gcol >> 6;
                    int d_ = gcol & 63;
                    size_t addr = (((size_t)(b_ * NHEADS + h_) * SQ) + qr) * DHEAD + d_;
                    float vt = __uint_as_float(f2tf32(v));
                    if (z == 0) g_qh[addr] = vt;
                    else if (z == 1) g_kh[addr] = vt;
                    else g_vh[addr] = vt;
                } else {
                    out[(size_t)grow * DMODEL + gcol] = v;
                }
            }
            __syncwarp();
        }
    }
}

// ---------------------------------------------------------------------------
// Flash attention v4 (R6 best): K/V/Q arrive as tf32 bits -> no conversions.
// Register-resident S/O, cp.async double-buffered K/V.
//
// m16n8k8 fragment layouts (g = lane>>2, q = lane&3):
//   A(16x8): a0=(g,q) a1=(g+8,q) a2=(g,q+4) a3=(g+8,q+4)
//   B(8x8) col-major: b0=(k=q,n=g) b1=(k=q+4,n=g)
//   C(16x8): c0=(g,2q) c1=(g,2q+1) c2=(g+8,2q) c3=(g+8,2q+1)
// ---------------------------------------------------------------------------
#define KLD 68
#define VLD 72
#define FL_KSZ (64 * KLD)
#define FL_VSZ (64 * VLD)
#define FLASH_SMEM ((2 * FL_KSZ + 2 * FL_VSZ) * (int)sizeof(float))  // 71680

__global__ __launch_bounds__(256)
void flash_attn_kernel()
{
    extern __shared__ float sm[];
    float* Ksm = sm;                  // [2][64][KLD]; also Q staging (128 x KLD)
    float* Vsm = sm + 2 * FL_KSZ;     // [2][64][VLD]

    const int q0  = blockIdx.x * 128;
    const int h   = blockIdx.y;
    const int b   = blockIdx.z;
    const int tid = threadIdx.x;
    const int wid = tid >> 5;
    const int lane = tid & 31;
    const int g = lane >> 2;
    const int q = lane & 3;

    const float* Qg = g_qh + (((size_t)(b * NHEADS + h) * SQ) + q0) * DHEAD;
    const float* Kg = g_kh + ((size_t)(b * NHEADS + h) * SK) * DHEAD;
    const float* Vg = g_vh + ((size_t)(b * NHEADS + h) * SK) * DHEAD;

#pragma unroll
    for (int i = 0; i < 8; i++) {
        int idx = tid + i * 256;
        int r = idx >> 4, c4 = idx & 15;
        cp_async16(&Ksm[r * KLD + c4 * 4], Qg + (size_t)r * DHEAD + c4 * 4);
    }
    cp_commit();
    cp_wait<0>();
    __syncthreads();

    // Q is tf32 bits; * 0.125 (2^-3) is exact and stays tf32 -> no cvt needed.
    uint32_t qa[8][4];
    {
        const float* Qw = Ksm + (wid * 16) * KLD;
#pragma unroll
        for (int kc = 0; kc < 8; kc++) {
            qa[kc][0] = __float_as_uint(0.125f * Qw[g * KLD + kc * 8 + q]);
            qa[kc][1] = __float_as_uint(0.125f * Qw[(g + 8) * KLD + kc * 8 + q]);
            qa[kc][2] = __float_as_uint(0.125f * Qw[g * KLD + kc * 8 + q + 4]);
            qa[kc][3] = __float_as_uint(0.125f * Qw[(g + 8) * KLD + kc * 8 + q + 4]);
        }
    }
    __syncthreads();   // everyone done reading Q before K overwrites

#define FL_PREFETCH(J, BUF)                                                         \
    {                                                                               \
        _Pragma("unroll")                                                           \
        for (int i = 0; i < 4; i++) {                                               \
            int idx = tid + i * 256;                                                \
            int r = idx >> 4, c4 = idx & 15;                                        \
            cp_async16(&Ksm[(BUF) * FL_KSZ + r * KLD + c4 * 4],                     \
                       Kg + (size_t)((J) * 64 + r) * DHEAD + c4 * 4);               \
            cp_async16(&Vsm[(BUF) * FL_VSZ + r * VLD + c4 * 4],                     \
                       Vg + (size_t)((J) * 64 + r) * DHEAD + c4 * 4);               \
        }                                                                           \
        cp_commit();                                                                \
    }

    FL_PREFETCH(0, 0);
    FL_PREFETCH(1, 1);

    float oacc[8][4];
#pragma unroll
    for (int nb = 0; nb < 8; nb++)
#pragma unroll
        for (int t = 0; t < 4; t++) oacc[nb][t] = 0.0f;

    float m0r = -CUDART_INF_F, m1r = -CUDART_INF_F;
    float l0r = 0.0f, l1r = 0.0f;

    const int NT = SK / 64;  // 32
    for (int j = 0; j < NT; j++) {
        if (j + 1 < NT) cp_wait<1>(); else cp_wait<0>();
        __syncthreads();

        const int buf = j & 1;
        const uint32_t* Kb = (const uint32_t*)(Ksm + buf * FL_KSZ);
        const uint32_t* Vb = (const uint32_t*)(Vsm + buf * FL_VSZ);

        float sacc[8][4];
#pragma unroll
        for (int nb = 0; nb < 8; nb++) {
#pragma unroll
            for (int t = 0; t < 4; t++) sacc[nb][t] = 0.0f;
#pragma unroll
            for (int kc = 0; kc < 8; kc++) {
                uint32_t b0 = Kb[(nb * 8 + g) * KLD + kc * 8 + q];
                uint32_t b1 = Kb[(nb * 8 + g) * KLD + kc * 8 + q + 4];
                mma_tf32(sacc[nb], qa[kc], b0, b1);
            }
        }

        float mx0 = -CUDART_INF_F, mx1 = -CUDART_INF_F;
#pragma unroll
        for (int nb = 0; nb < 8; nb++) {
            mx0 = fmaxf(mx0, fmaxf(sacc[nb][0], sacc[nb][1]));
            mx1 = fmaxf(mx1, fmaxf(sacc[nb][2], sacc[nb][3]));
        }
        mx0 = fmaxf(mx0, __shfl_xor_sync(0xffffffffu, mx0, 1));
        mx0 = fmaxf(mx0, __shfl_xor_sync(0xffffffffu, mx0, 2));
        mx1 = fmaxf(mx1, __shfl_xor_sync(0xffffffffu, mx1, 1));
        mx1 = fmaxf(mx1, __shfl_xor_sync(0xffffffffu, mx1, 2));

        float mn0 = fmaxf(m0r, mx0), mn1 = fmaxf(m1r, mx1);
        float al0 = __expf(m0r - mn0), al1 = __expf(m1r - mn1);
        m0r = mn0; m1r = mn1;

        float s0 = 0.0f, s1 = 0.0f;
#pragma unroll
        for (int nb = 0; nb < 8; nb++) {
            sacc[nb][0] = __expf(sacc[nb][0] - mn0); s0 += sacc[nb][0];
            sacc[nb][1] = __expf(sacc[nb][1] - mn0); s0 += sacc[nb][1];
            sacc[nb][2] = __expf(sacc[nb][2] - mn1); s1 += sacc[nb][2];
            sacc[nb][3] = __expf(sacc[nb][3] - mn1); s1 += sacc[nb][3];
        }
        s0 += __shfl_xor_sync(0xffffffffu, s0, 1);
        s0 += __shfl_xor_sync(0xffffffffu, s0, 2);
        s1 += __shfl_xor_sync(0xffffffffu, s1, 1);
        s1 += __shfl_xor_sync(0xffffffffu, s1, 2);
        l0r = l0r * al0 + s0;
        l1r = l1r * al1 + s1;

#pragma unroll
        for (int nb = 0; nb < 8; nb++) {
            oacc[nb][0] *= al0; oacc[nb][1] *= al0;
            oacc[nb][2] *= al1; oacc[nb][3] *= al1;
        }

        const int src1 = (lane & ~3) | (q >> 1);
        const int src2 = src1 + 2;
        const bool odd = (q & 1);
#pragma unroll
        for (int kc = 0; kc < 8; kc++) {
            float e, o;
            uint32_t pa[4];
            e = __shfl_sync(0xffffffffu, sacc[kc][0], src1);
            o = __shfl_sync(0xffffffffu, sacc[kc][1], src1);
            pa[0] = f2tf32(odd ? o : e);
            e = __shfl_sync(0xffffffffu, sacc[kc][2], src1);
            o = __shfl_sync(0xffffffffu, sacc[kc][3], src1);
            pa[1] = f2tf32(odd ? o : e);
            e = __shfl_sync(0xffffffffu, sacc[kc][0], src2);
            o = __shfl_sync(0xffffffffu, sacc[kc][1], src2);
            pa[2] = f2tf32(odd ? o : e);
            e = __shfl_sync(0xffffffffu, sacc[kc][2], src2);
            o = __shfl_sync(0xffffffffu, sacc[kc][3], src2);
            pa[3] = f2tf32(odd ? o : e);
#pragma unroll
            for (int nb = 0; nb < 8; nb++) {
                uint32_t vb0 = Vb[(kc * 8 + q) * VLD + nb * 8 + g];
                uint32_t vb1 = Vb[(kc * 8 + q + 4) * VLD + nb * 8 + g];
                mma_tf32(oacc[nb], pa, vb0, vb1);
            }
        }

        __syncthreads();
        if (j + 2 < NT) FL_PREFETCH(j + 2, buf);
    }
#undef FL_PREFETCH

    // normalize + write merged [b, q, h*64+d] as tf32 bits
    float inv0 = 1.0f / l0r, inv1 = 1.0f / l1r;
    int r0 = q0 + wid * 16 + g;
    float* og0 = g_attn + ((size_t)(b * SQ + r0) * DMODEL) + h * DHEAD;
    float* og1 = g_attn + ((size_t)(b * SQ + r0 + 8) * DMODEL) + h * DHEAD;
#pragma unroll
    for (int nb = 0; nb < 8; nb++) {
        float2 v0 = make_float2(__uint_as_float(f2tf32(oacc[nb][0] * inv0)),
                                __uint_as_float(f2tf32(oacc[nb][1] * inv0)));
        float2 v1 = make_float2(__uint_as_float(f2tf32(oacc[nb][2] * inv1)),
                                __uint_as_float(f2tf32(oacc[nb][3] * inv1)));
        *(float2*)(og0 + nb * 8 + 2 * q) = v0;
        *(float2*)(og1 + nb * 8 + 2 * q) = v1;
    }
}

// ---------------------------------------------------------------------------
// Launch
// ---------------------------------------------------------------------------
extern "C" void kernel_launch(void* const* d_in, const int* in_sizes, int n_in,
                              void* d_out, int out_size)
{
    const float* q  = (const float*)d_in[0];
    const float* k  = (const float*)d_in[1];
    const float* v  = (const float*)d_in[2];
    const float* Wq = (const float*)d_in[3];
    const float* bq = (const float*)d_in[4];
    const float* Wk = (const float*)d_in[5];
    const float* bk = (const float*)d_in[6];
    const float* Wv = (const float*)d_in[7];
    const float* bv = (const float*)d_in[8];
    const float* Wo = (const float*)d_in[9];
    const float* bo = (const float*)d_in[10];
    float* out = (float*)d_out;

    static bool attr_done = false;
    if (!attr_done) {
        cudaFuncSetAttribute(gemm_tf32_kernel<0>, cudaFuncAttributeMaxDynamicSharedMemorySize, GEMM_SMEM);
        cudaFuncSetAttribute(gemm_tf32_kernel<1>, cudaFuncAttributeMaxDynamicSharedMemorySize, GEMM_SMEM);
        cudaFuncSetAttribute(flash_attn_kernel, cudaFuncAttributeMaxDynamicSharedMemorySize, FLASH_SMEM);
        attr_done = true;
    }

    // 1. Round inputs + weights to tf32 bits (one launch)
    {
        dim3 cgrid(4096, 7);
        preconvert_kernel<<<cgrid, 256>>>((const float4*)q, (const float4*)k, (const float4*)v,
                                          (const float4*)Wq, (const float4*)Wk,
                                          (const float4*)Wv, (const float4*)Wo);
    }

    // 2. Batched Q/K/V projections -> head-major tf32 scratch
    {
        dim3 ggrid(DMODEL / 128, MROWS / 128, 3);   // (8, 32, 3)
        gemm_tf32_kernel<0><<<ggrid, 128, GEMM_SMEM>>>(bq, bk, bv, nullptr);
    }

    // 3. Flash attention
    {
        dim3 fgrid(SQ / 128, NHEADS, NBATCH);       // (16, 16, 2)
        flash_attn_kernel<<<fgrid, 256, FLASH_SMEM>>>();
    }

    // 4. Output projection
    {
        dim3 ggrid(DMODEL / 128, MROWS / 128, 1);   // (8, 32)
        gemm_tf32_kernel<1><<<ggrid, 128, GEMM_SMEM>>>(bo, nullptr, nullptr, out);
    }
}

// round 10
// speedup vs baseline: 2.7545x; 2.7545x over previous
#include <cuda_runtime.h>
#include <cuda_fp16.h>
#include <mma.h>
#include <math_constants.h>
#include <cstdint>

using namespace nvcuda;

#define DMODEL 1024
#define NHEADS 16
#define DHEAD  64
#define NBATCH 2
#define SQ     2048
#define SK     2048
#define MROWS  (NBATCH * SQ)   // 4096

// ---------------------------------------------------------------------------
// Scratch (device globals: no allocation allowed)
// ---------------------------------------------------------------------------
__device__ __half g_qh[(size_t)NBATCH * NHEADS * SQ * DHEAD];   // [b,h,q,d], pre-scaled by 0.125
__device__ __half g_kh[(size_t)NBATCH * NHEADS * SK * DHEAD];   // [b,h,s,d]
__device__ __half g_vt[(size_t)NBATCH * NHEADS * DHEAD * SK];   // [b,h,d,s]  TRANSPOSED
__device__ __half g_attn[(size_t)NBATCH * SQ * DMODEL];          // [b,q,h*64+d]
__device__ __half g_act[(size_t)3 * MROWS * DMODEL];             // fp16(q,k,v)
__device__ __half g_w[(size_t)3 * DMODEL * DMODEL];              // fp16(Wq,Wk,Wv)  [k][n]
__device__ __half g_wo[(size_t)DMODEL * DMODEL];                 // fp16(Wo)        [k][n]

// ---------------------------------------------------------------------------
// helpers
// ---------------------------------------------------------------------------
__device__ __forceinline__ void cp_async16(void* smem, const void* gmem) {
    uint32_t s = (uint32_t)__cvta_generic_to_shared(smem);
    asm volatile("cp.async.cg.shared.global [%0], [%1], 16;\n" :: "r"(s), "l"(gmem));
}
__device__ __forceinline__ void cp_commit() { asm volatile("cp.async.commit_group;\n"); }
template<int N> __device__ __forceinline__ void cp_wait() {
    asm volatile("cp.async.wait_group %0;\n" :: "n"(N));
}
// pack two f32 -> f16x2 (first source goes to HIGH half)
__device__ __forceinline__ uint32_t pack_f16x2(float hi, float lo) {
    uint32_t r; asm("cvt.rn.f16x2.f32 %0, %1, %2;" : "=r"(r) : "f"(hi), "f"(lo)); return r;
}
// fp16 MMA m16n8k16, fp32 accumulate
__device__ __forceinline__ void mma_f16(float c[4], const uint32_t a[4], uint32_t b0, uint32_t b1) {
    asm volatile("mma.sync.aligned.m16n8k16.row.col.f32.f16.f16.f32 "
        "{%0,%1,%2,%3}, {%4,%5,%6,%7}, {%8,%9}, {%0,%1,%2,%3};\n"
        : "+f"(c[0]), "+f"(c[1]), "+f"(c[2]), "+f"(c[3])
        : "r"(a[0]), "r"(a[1]), "r"(a[2]), "r"(a[3]), "r"(b0), "r"(b1));
}

// ---------------------------------------------------------------------------
// Preconvert: inputs + weights -> fp16. grid (4096, 7) x 256.
// y=0..2 -> q,k,v (1048576 float4); y=3..6 -> Wq,Wk,Wv,Wo (262144 float4)
// ---------------------------------------------------------------------------
__global__ __launch_bounds__(256)
void preconvert_kernel(const float4* __restrict__ q, const float4* __restrict__ k,
                       const float4* __restrict__ v, const float4* __restrict__ wq,
                       const float4* __restrict__ wk, const float4* __restrict__ wv,
                       const float4* __restrict__ wo)
{
    const int y = blockIdx.y;
    const float4* src;
    __half* dst;
    int n4;
    if (y < 3) {
        src = (y == 0) ? q : (y == 1) ? k : v;
        dst = g_act + (size_t)y * (MROWS * DMODEL);
        n4 = MROWS * DMODEL / 4;
    } else {
        src = (y == 3) ? wq : (y == 4) ? wk : (y == 5) ? wv : wo;
        dst = (y < 6) ? g_w + (size_t)(y - 3) * (DMODEL * DMODEL) : g_wo;
        n4 = DMODEL * DMODEL / 4;
    }
    int idx = blockIdx.x * 256 + threadIdx.x;
    if (idx < n4) {
        float4 s = src[idx];
        uint2 u;
        u.x = pack_f16x2(s.y, s.x);
        u.y = pack_f16x2(s.w, s.z);
        *(uint2*)(dst + 4 * (size_t)idx) = u;
    }
}

// ---------------------------------------------------------------------------
// FP16 GEMM: CTA 128x128, 4 warps, warp tile 64x64 (4x4 wmma 16x16x16),
// BK=32, cp.async double buffering. fp32 accumulate.
// MODE 0: batched projections (grid.z selects act/W/bias):
//         z=0 -> g_qh (x0.125), z=1 -> g_kh, z=2 -> g_vt (transposed).
// MODE 1: out = g_attn @ g_wo + bo, fp32 row-major.
// ---------------------------------------------------------------------------
#define G_ALD 40     // halves per A row (32 + 8 pad), 80B
#define G_BLD 136    // halves per B row (128 + 8 pad), 272B
#define G_ASZ (128 * G_ALD)
#define G_BSZ (32 * G_BLD)
#define GEMM_SMEM ((2 * G_ASZ + 2 * G_BSZ) * (int)sizeof(__half))  // 37888

template<int MODE>
__global__ __launch_bounds__(128)
void gemm_f16_kernel(const float* __restrict__ bias0,
                     const float* __restrict__ bias1,
                     const float* __restrict__ bias2,
                     float* __restrict__ out)
{
    extern __shared__ __half gsm[];
    __half* Asm = gsm;                  // [2][128][40]
    __half* Bsm = gsm + 2 * G_ASZ;      // [2][32][136]
    __shared__ float stage[4][256];

    const int z = blockIdx.z;
    const __half* Ap   = (MODE == 1) ? g_attn : g_act + (size_t)z * (MROWS * DMODEL);
    const __half* W    = (MODE == 1) ? g_wo   : g_w   + (size_t)z * (DMODEL * DMODEL);
    const float* bias  = (MODE == 1) ? bias0  : (z == 0) ? bias0 : (z == 1) ? bias1 : bias2;

    const int tid    = threadIdx.x;
    const int wid    = tid >> 5;
    const int lane   = tid & 31;
    const int warp_m = wid >> 1;
    const int warp_n = wid & 1;
    const int m0 = blockIdx.y * 128;
    const int n0 = blockIdx.x * 128;

    wmma::fragment<wmma::accumulator, 16, 16, 16, float> acc[4][4];
#pragma unroll
    for (int i = 0; i < 4; i++)
#pragma unroll
        for (int j = 0; j < 4; j++)
            wmma::fill_fragment(acc[i][j], 0.0f);

#define GEMM_PREFETCH(IT, BUF)                                                      \
    {                                                                               \
        int k0 = (IT) * 32;                                                         \
        _Pragma("unroll")                                                           \
        for (int i = 0; i < 4; i++) {                                               \
            int idx = tid + i * 128;                                                \
            int r = idx >> 2, c = idx & 3;                                          \
            cp_async16(&Asm[(BUF) * G_ASZ + r * G_ALD + c * 8],                     \
                       Ap + (size_t)(m0 + r) * DMODEL + k0 + c * 8);                \
        }                                                                           \
        _Pragma("unroll")                                                           \
        for (int i = 0; i < 4; i++) {                                               \
            int idx = tid + i * 128;                                                \
            int r = idx >> 4, c = idx & 15;                                         \
            cp_async16(&Bsm[(BUF) * G_BSZ + r * G_BLD + c * 8],                     \
                       W + (size_t)(k0 + r) * DMODEL + n0 + c * 8);                 \
        }                                                                           \
        cp_commit();                                                                \
    }

    GEMM_PREFETCH(0, 0);
    GEMM_PREFETCH(1, 1);

    for (int it = 0; it < 32; it++) {
        if (it + 1 < 32) cp_wait<1>(); else cp_wait<0>();
        __syncthreads();

        const int buf = it & 1;
        const __half* Asb = Asm + buf * G_ASZ;
        const __half* Bsb = Bsm + buf * G_BSZ;

#pragma unroll
        for (int kf = 0; kf < 2; kf++) {
            wmma::fragment<wmma::matrix_a, 16, 16, 16, __half, wmma::row_major> a[4];
            wmma::fragment<wmma::matrix_b, 16, 16, 16, __half, wmma::row_major> b[4];
#pragma unroll
            for (int i = 0; i < 4; i++)
                wmma::load_matrix_sync(a[i], Asb + (warp_m * 64 + i * 16) * G_ALD + kf * 16, G_ALD);
#pragma unroll
            for (int j = 0; j < 4; j++)
                wmma::load_matrix_sync(b[j], Bsb + (kf * 16) * G_BLD + warp_n * 64 + j * 16, G_BLD);
#pragma unroll
            for (int i = 0; i < 4; i++)
#pragma unroll
                for (int j = 0; j < 4; j++)
                    wmma::mma_sync(acc[i][j], a[i], b[j], acc[i][j]);
        }
        __syncthreads();
        if (it + 2 < 32) GEMM_PREFETCH(it + 2, buf);
    }
#undef GEMM_PREFETCH

    // Epilogue
#pragma unroll
    for (int i = 0; i < 4; i++) {
#pragma unroll
        for (int j = 0; j < 4; j++) {
            wmma::store_matrix_sync(&stage[wid][0], acc[i][j], 16, wmma::mem_row_major);
            __syncwarp();
            int grow0 = m0 + warp_m * 64 + i * 16;
            int gcol0 = n0 + warp_n * 64 + j * 16;
#pragma unroll
            for (int t = lane; t < 256; t += 32) {
                int r = t >> 4, c = t & 15;
                int grow = grow0 + r;
                int gcol = gcol0 + c;
                float v = stage[wid][t] + bias[gcol];
                if (MODE == 0) {
                    int b_ = grow >> 11;
                    int qr = grow & 2047;
                    int h_ = gcol >> 6;
                    int d_ = gcol & 63;
                    if (z == 0) {
                        size_t addr = (((size_t)(b_ * NHEADS + h_) * SQ) + qr) * DHEAD + d_;
                        g_qh[addr] = __float2half(v * 0.125f);   // fold in 1/sqrt(64)
                    } else if (z == 1) {
                        size_t addr = (((size_t)(b_ * NHEADS + h_) * SK) + qr) * DHEAD + d_;
                        g_kh[addr] = __float2half(v);
                    } else {
                        size_t addr = (((size_t)(b_ * NHEADS + h_) * DHEAD) + d_) * SK + qr;
                        g_vt[addr] = __float2half(v);            // transposed
                    }
                } else {
                    out[(size_t)grow * DMODEL + gcol] = v;
                }
            }
            __syncwarp();
        }
    }
}

// ---------------------------------------------------------------------------
// Flash attention fp16: register-resident S/O via mma.m16n8k16.f16.
// One CTA = 128 query rows (8 warps x 16), 64-key tiles, cp.async double-
// buffered K (row-major [s][d]) and Vt (transposed [d][s]).
//
// m16n8k16 fragment layouts (g = lane>>2, q = lane&3):
//   A: a0=(g, 2q:2q+1) a1=(g+8, 2q:2q+1) a2=(g, 2q+8:2q+9) a3=(g+8, 2q+8:2q+9)
//   B (col-major kxn): b0=(k=2q:2q+1, n=g), b1=(k=2q+8:2q+9, n=g)
//   C: c0=(g,2q) c1=(g,2q+1) c2=(g+8,2q) c3=(g+8,2q+1)
// => P accumulator pairs pack DIRECTLY into A fragments via cvt.f16x2 (no shuffles)
// ---------------------------------------------------------------------------
#define FLD 72                       // halves per row (64 + 8 pad), 144B
#define FL_TSZ (64 * FLD)            // 4608 halves per tile
#define FLASH_SMEM ((4 * FL_TSZ) * (int)sizeof(__half))   // 36864

__global__ __launch_bounds__(256)
void flash_attn_kernel()
{
    extern __shared__ __half fsm[];
    __half* Ksm = fsm;                 // [2][64][FLD]; doubles as Q staging [128][FLD]
    __half* Vsm = fsm + 2 * FL_TSZ;    // [2][64][FLD] (Vt tiles)

    const int q0  = blockIdx.x * 128;
    const int h   = blockIdx.y;
    const int b   = blockIdx.z;
    const int tid = threadIdx.x;
    const int wid = tid >> 5;
    const int lane = tid & 31;
    const int g = lane >> 2;
    const int q = lane & 3;

    const __half* Qg = g_qh + (((size_t)(b * NHEADS + h) * SQ) + q0) * DHEAD;
    const __half* Kg = g_kh + ((size_t)(b * NHEADS + h) * SK) * DHEAD;
    const __half* Vg = g_vt + ((size_t)(b * NHEADS + h) * DHEAD) * SK;

    // ---- Stage Q tile (128 x 64 halves) into Ksm area, build A fragments ----
#pragma unroll
    for (int i = 0; i < 4; i++) {
        int idx = tid + i * 256;
        int r = idx >> 3, c = idx & 7;
        cp_async16(&Ksm[r * FLD + c * 8], Qg + (size_t)r * DHEAD + c * 8);
    }
    cp_commit();
    cp_wait<0>();
    __syncthreads();

    uint32_t qa[4][4];
    {
        const uint32_t* Qw = (const uint32_t*)Ksm;
        const int r0 = wid * 16 + g;
#pragma unroll
        for (int kc = 0; kc < 4; kc++) {
            qa[kc][0] = Qw[(r0)     * (FLD / 2) + kc * 8 + q];
            qa[kc][1] = Qw[(r0 + 8) * (FLD / 2) + kc * 8 + q];
            qa[kc][2] = Qw[(r0)     * (FLD / 2) + kc * 8 + q + 4];
            qa[kc][3] = Qw[(r0 + 8) * (FLD / 2) + kc * 8 + q + 4];
        }
    }
    __syncthreads();   // everyone done reading Q before K overwrites

#define FL_PREFETCH(J, BUF)                                                         \
    {                                                                               \
        _Pragma("unroll")                                                           \
        for (int i = 0; i < 2; i++) {                                               \
            int idx = tid + i * 256;                                                \
            int r = idx >> 3, c = idx & 7;                                          \
            cp_async16(&Ksm[(BUF) * FL_TSZ + r * FLD + c * 8],                      \
                       Kg + (size_t)((J) * 64 + r) * DHEAD + c * 8);                \
            cp_async16(&Vsm[(BUF) * FL_TSZ + r * FLD + c * 8],                      \
                       Vg + (size_t)r * SK + (J) * 64 + c * 8);                     \
        }                                                                           \
        cp_commit();                                                                \
    }

    FL_PREFETCH(0, 0);
    FL_PREFETCH(1, 1);

    float oacc[8][4];
#pragma unroll
    for (int nb = 0; nb < 8; nb++)
#pragma unroll
        for (int t = 0; t < 4; t++) oacc[nb][t] = 0.0f;

    float m0r = -CUDART_INF_F, m1r = -CUDART_INF_F;
    float l0r = 0.0f, l1r = 0.0f;

    const int NT = SK / 64;  // 32
    for (int j = 0; j < NT; j++) {
        if (j + 1 < NT) cp_wait<1>(); else cp_wait<0>();
        __syncthreads();

        const int buf = j & 1;
        const uint32_t* Kb = (const uint32_t*)(Ksm + buf * FL_TSZ);
        const uint32_t* Vb = (const uint32_t*)(Vsm + buf * FL_TSZ);

        // ---- S = (Q*0.125) K^T  (Q pre-scaled) ----
        float sacc[8][4];
#pragma unroll
        for (int nb = 0; nb < 8; nb++) {
#pragma unroll
            for (int t = 0; t < 4; t++) sacc[nb][t] = 0.0f;
#pragma unroll
            for (int kc = 0; kc < 4; kc++) {
                uint32_t b0 = Kb[(nb * 8 + g) * (FLD / 2) + kc * 8 + q];
                uint32_t b1 = Kb[(nb * 8 + g) * (FLD / 2) + kc * 8 + q + 4];
                mma_f16(sacc[nb], qa[kc], b0, b1);
            }
        }

        // ---- online softmax on registers (rows g and g+8) ----
        float mx0 = -CUDART_INF_F, mx1 = -CUDART_INF_F;
#pragma unroll
        for (int nb = 0; nb < 8; nb++) {
            mx0 = fmaxf(mx0, fmaxf(sacc[nb][0], sacc[nb][1]));
            mx1 = fmaxf(mx1, fmaxf(sacc[nb][2], sacc[nb][3]));
        }
        mx0 = fmaxf(mx0, __shfl_xor_sync(0xffffffffu, mx0, 1));
        mx0 = fmaxf(mx0, __shfl_xor_sync(0xffffffffu, mx0, 2));
        mx1 = fmaxf(mx1, __shfl_xor_sync(0xffffffffu, mx1, 1));
        mx1 = fmaxf(mx1, __shfl_xor_sync(0xffffffffu, mx1, 2));

        float mn0 = fmaxf(m0r, mx0), mn1 = fmaxf(m1r, mx1);
        float al0 = __expf(m0r - mn0), al1 = __expf(m1r - mn1);
        m0r = mn0; m1r = mn1;

        float s0 = 0.0f, s1 = 0.0f;
#pragma unroll
        for (int nb = 0; nb < 8; nb++) {
            sacc[nb][0] = __expf(sacc[nb][0] - mn0); s0 += sacc[nb][0];
            sacc[nb][1] = __expf(sacc[nb][1] - mn0); s0 += sacc[nb][1];
            sacc[nb][2] = __expf(sacc[nb][2] - mn1); s1 += sacc[nb][2];
            sacc[nb][3] = __expf(sacc[nb][3] - mn1); s1 += sacc[nb][3];
        }
        s0 += __shfl_xor_sync(0xffffffffu, s0, 1);
        s0 += __shfl_xor_sync(0xffffffffu, s0, 2);
        s1 += __shfl_xor_sync(0xffffffffu, s1, 1);
        s1 += __shfl_xor_sync(0xffffffffu, s1, 2);
        l0r = l0r * al0 + s0;
        l1r = l1r * al1 + s1;

#pragma unroll
        for (int nb = 0; nb < 8; nb++) {
            oacc[nb][0] *= al0; oacc[nb][1] *= al0;
            oacc[nb][2] *= al1; oacc[nb][3] *= al1;
        }

        // ---- O += P @ Vt : P accum pairs pack directly into A frags ----
#pragma unroll
        for (int kc = 0; kc < 4; kc++) {
            uint32_t pa[4];
            pa[0] = pack_f16x2(sacc[2 * kc][1],     sacc[2 * kc][0]);
            pa[1] = pack_f16x2(sacc[2 * kc][3],     sacc[2 * kc][2]);
            pa[2] = pack_f16x2(sacc[2 * kc + 1][1], sacc[2 * kc + 1][0]);
            pa[3] = pack_f16x2(sacc[2 * kc + 1][3], sacc[2 * kc + 1][2]);
#pragma unroll
            for (int nb = 0; nb < 8; nb++) {
                uint32_t vb0 = Vb[(nb * 8 + g) * (FLD / 2) + kc * 8 + q];
                uint32_t vb1 = Vb[(nb * 8 + g) * (FLD / 2) + kc * 8 + q + 4];
                mma_f16(oacc[nb], pa, vb0, vb1);
            }
        }

        __syncthreads();
        if (j + 2 < NT) FL_PREFETCH(j + 2, buf);
    }
#undef FL_PREFETCH

    // ---- normalize + write merged [b, q, h*64+d] as fp16 ----
    float inv0 = 1.0f / l0r, inv1 = 1.0f / l1r;
    int r0 = q0 + wid * 16 + g;
    uint32_t* og0 = (uint32_t*)(g_attn + ((size_t)(b * SQ + r0) * DMODEL) + h * DHEAD);
    uint32_t* og1 = (uint32_t*)(g_attn + ((size_t)(b * SQ + r0 + 8) * DMODEL) + h * DHEAD);
#pragma unroll
    for (int nb = 0; nb < 8; nb++) {
        og0[nb * 4 + q] = pack_f16x2(oacc[nb][1] * inv0, oacc[nb][0] * inv0);
        og1[nb * 4 + q] = pack_f16x2(oacc[nb][3] * inv1, oacc[nb][2] * inv1);
    }
}

// ---------------------------------------------------------------------------
// Launch
// ---------------------------------------------------------------------------
extern "C" void kernel_launch(void* const* d_in, const int* in_sizes, int n_in,
                              void* d_out, int out_size)
{
    const float* q  = (const float*)d_in[0];
    const float* k  = (const float*)d_in[1];
    const float* v  = (const float*)d_in[2];
    const float* Wq = (const float*)d_in[3];
    const float* bq = (const float*)d_in[4];
    const float* Wk = (const float*)d_in[5];
    const float* bk = (const float*)d_in[6];
    const float* Wv = (const float*)d_in[7];
    const float* bv = (const float*)d_in[8];
    const float* Wo = (const float*)d_in[9];
    const float* bo = (const float*)d_in[10];
    float* out = (float*)d_out;

    static bool attr_done = false;
    if (!attr_done) {
        cudaFuncSetAttribute(gemm_f16_kernel<0>, cudaFuncAttributeMaxDynamicSharedMemorySize, GEMM_SMEM);
        cudaFuncSetAttribute(gemm_f16_kernel<1>, cudaFuncAttributeMaxDynamicSharedMemorySize, GEMM_SMEM);
        cudaFuncSetAttribute(flash_attn_kernel, cudaFuncAttributeMaxDynamicSharedMemorySize, FLASH_SMEM);
        attr_done = true;
    }

    // 1. Convert inputs + weights to fp16 (one launch)
    {
        dim3 cgrid(4096, 7);
        preconvert_kernel<<<cgrid, 256>>>((const float4*)q, (const float4*)k, (const float4*)v,
                                          (const float4*)Wq, (const float4*)Wk,
                                          (const float4*)Wv, (const float4*)Wo);
    }

    // 2. Batched Q/K/V projections -> head-major fp16 scratch (V transposed)
    {
        dim3 ggrid(DMODEL / 128, MROWS / 128, 3);   // (8, 32, 3)
        gemm_f16_kernel<0><<<ggrid, 128, GEMM_SMEM>>>(bq, bk, bv, nullptr);
    }

    // 3. Flash attention
    {
        dim3 fgrid(SQ / 128, NHEADS, NBATCH);       // (16, 16, 2)
        flash_attn_kernel<<<fgrid, 256, FLASH_SMEM>>>();
    }

    // 4. Output projection
    {
        dim3 ggrid(DMODEL / 128, MROWS / 128, 1);   // (8, 32)
        gemm_f16_kernel<1><<<ggrid, 128, GEMM_SMEM>>>(bo, nullptr, nullptr, out);
    }
}

// round 11
// speedup vs baseline: 2.8004x; 1.0167x over previous
#include <cuda_runtime.h>
#include <cuda_fp16.h>
#include <mma.h>
#include <math_constants.h>
#include <cstdint>

using namespace nvcuda;

#define DMODEL 1024
#define NHEADS 16
#define DHEAD  64
#define NBATCH 2
#define SQ     2048
#define SK     2048
#define MROWS  (NBATCH * SQ)   // 4096

// Q pre-scale: 1/sqrt(64) * log2(e)  (flash uses exp2)
#define QSCALE 0.18033688011112042f

// ---------------------------------------------------------------------------
// Scratch (device globals: no allocation allowed)
// ---------------------------------------------------------------------------
__device__ __half g_qh[(size_t)NBATCH * NHEADS * SQ * DHEAD];   // [b,h,q,d], pre-scaled
__device__ __half g_kh[(size_t)NBATCH * NHEADS * SK * DHEAD];   // [b,h,s,d]
__device__ __half g_vt[(size_t)NBATCH * NHEADS * DHEAD * SK];   // [b,h,d,s]  TRANSPOSED
__device__ __half g_attn[(size_t)NBATCH * SQ * DMODEL];          // [b,q,h*64+d]
__device__ __half g_act[(size_t)3 * MROWS * DMODEL];             // fp16(q,k,v)
__device__ __half g_w[(size_t)3 * DMODEL * DMODEL];              // fp16(Wq,Wk,Wv)  [k][n]
__device__ __half g_wo[(size_t)DMODEL * DMODEL];                 // fp16(Wo)        [k][n]

// ---------------------------------------------------------------------------
// helpers
// ---------------------------------------------------------------------------
__device__ __forceinline__ void cp_async16(void* smem, const void* gmem) {
    uint32_t s = (uint32_t)__cvta_generic_to_shared(smem);
    asm volatile("cp.async.cg.shared.global [%0], [%1], 16;\n" :: "r"(s), "l"(gmem));
}
__device__ __forceinline__ void cp_commit() { asm volatile("cp.async.commit_group;\n"); }
template<int N> __device__ __forceinline__ void cp_wait() {
    asm volatile("cp.async.wait_group %0;\n" :: "n"(N));
}
__device__ __forceinline__ uint32_t pack_f16x2(float hi, float lo) {
    uint32_t r; asm("cvt.rn.f16x2.f32 %0, %1, %2;" : "=r"(r) : "f"(hi), "f"(lo)); return r;
}
__device__ __forceinline__ void mma_f16(float c[4], const uint32_t a[4], uint32_t b0, uint32_t b1) {
    asm volatile("mma.sync.aligned.m16n8k16.row.col.f32.f16.f16.f32 "
        "{%0,%1,%2,%3}, {%4,%5,%6,%7}, {%8,%9}, {%0,%1,%2,%3};\n"
        : "+f"(c[0]), "+f"(c[1]), "+f"(c[2]), "+f"(c[3])
        : "r"(a[0]), "r"(a[1]), "r"(a[2]), "r"(a[3]), "r"(b0), "r"(b1));
}

// ---------------------------------------------------------------------------
// Preconvert: inputs + weights -> fp16. grid (4096, 7) x 256.
// ---------------------------------------------------------------------------
__global__ __launch_bounds__(256)
void preconvert_kernel(const float4* __restrict__ q, const float4* __restrict__ k,
                       const float4* __restrict__ v, const float4* __restrict__ wq,
                       const float4* __restrict__ wk, const float4* __restrict__ wv,
                       const float4* __restrict__ wo)
{
    const int y = blockIdx.y;
    const float4* src;
    __half* dst;
    int n4;
    if (y < 3) {
        src = (y == 0) ? q : (y == 1) ? k : v;
        dst = g_act + (size_t)y * (MROWS * DMODEL);
        n4 = MROWS * DMODEL / 4;
    } else {
        src = (y == 3) ? wq : (y == 4) ? wk : (y == 5) ? wv : wo;
        dst = (y < 6) ? g_w + (size_t)(y - 3) * (DMODEL * DMODEL) : g_wo;
        n4 = DMODEL * DMODEL / 4;
    }
    int idx = blockIdx.x * 256 + threadIdx.x;
    if (idx < n4) {
        float4 s = src[idx];
        uint2 u;
        u.x = pack_f16x2(s.y, s.x);
        u.y = pack_f16x2(s.w, s.z);
        *(uint2*)(dst + 4 * (size_t)idx) = u;
    }
}

// ---------------------------------------------------------------------------
// FP16 GEMM v2: CTA 128x128, 8 warps (warp tile 32x64), BK=32, TRIPLE-buffered
// cp.async with one __syncthreads per k-step. fp32 accumulate.
// MODE 0: batched projections (z: 0->g_qh x QSCALE, 1->g_kh, 2->g_vt transposed)
// MODE 1: out = g_attn @ g_wo + bo (fp32)
// ---------------------------------------------------------------------------
#define G_ALD 40     // halves per A row (32 + 8 pad)
#define G_BLD 136    // halves per B row (128 + 8 pad)
#define G_ASZ (128 * G_ALD)
#define G_BSZ (32 * G_BLD)
#define GEMM_SMEM (3 * (G_ASZ + G_BSZ) * (int)sizeof(__half))  // 56832

template<int MODE>
__global__ __launch_bounds__(256, 2)
void gemm_f16_kernel(const float* __restrict__ bias0,
                     const float* __restrict__ bias1,
                     const float* __restrict__ bias2,
                     float* __restrict__ out)
{
    extern __shared__ __half gsm[];
    __half* Asm = gsm;                  // [3][128][40]
    __half* Bsm = gsm + 3 * G_ASZ;      // [3][32][136]
    __shared__ float stage[8][256];

    const int z = blockIdx.z;
    const __half* Ap   = (MODE == 1) ? g_attn : g_act + (size_t)z * (MROWS * DMODEL);
    const __half* W    = (MODE == 1) ? g_wo   : g_w   + (size_t)z * (DMODEL * DMODEL);
    const float* bias  = (MODE == 1) ? bias0  : (z == 0) ? bias0 : (z == 1) ? bias1 : bias2;

    const int tid    = threadIdx.x;
    const int wid    = tid >> 5;
    const int lane   = tid & 31;
    const int warp_m = wid >> 1;     // 0..3 (32 rows each)
    const int warp_n = wid & 1;      // 0..1 (64 cols each)
    const int m0 = blockIdx.y * 128;
    const int n0 = blockIdx.x * 128;

    wmma::fragment<wmma::accumulator, 16, 16, 16, float> acc[2][4];
#pragma unroll
    for (int i = 0; i < 2; i++)
#pragma unroll
        for (int j = 0; j < 4; j++)
            wmma::fill_fragment(acc[i][j], 0.0f);

#define GEMM_PREFETCH(IT, BUF)                                                      \
    {                                                                               \
        int k0 = (IT) * 32;                                                         \
        _Pragma("unroll")                                                           \
        for (int i = 0; i < 2; i++) {                                               \
            int idx = tid + i * 256;                                                \
            int r = idx >> 2, c = idx & 3;                                          \
            cp_async16(&Asm[(BUF) * G_ASZ + r * G_ALD + c * 8],                     \
                       Ap + (size_t)(m0 + r) * DMODEL + k0 + c * 8);                \
        }                                                                           \
        _Pragma("unroll")                                                           \
        for (int i = 0; i < 2; i++) {                                               \
            int idx = tid + i * 256;                                                \
            int r = idx >> 4, c = idx & 15;                                         \
            cp_async16(&Bsm[(BUF) * G_BSZ + r * G_BLD + c * 8],                     \
                       W + (size_t)(k0 + r) * DMODEL + n0 + c * 8);                 \
        }                                                                           \
        cp_commit();                                                                \
    }

    GEMM_PREFETCH(0, 0);
    GEMM_PREFETCH(1, 1);

    int buf = 0;
    for (int it = 0; it < 32; it++) {
        if (it + 1 < 32) cp_wait<1>(); else cp_wait<0>();
        __syncthreads();
        // prefetch into the stage retired at it-1 (fenced by the barrier above)
        if (it + 2 < 32) {
            int nbuf = (buf + 2 >= 3) ? buf - 1 : buf + 2;
            GEMM_PREFETCH(it + 2, nbuf);
        }

        const __half* Asb = Asm + buf * G_ASZ;
        const __half* Bsb = Bsm + buf * G_BSZ;

#pragma unroll
        for (int kf = 0; kf < 2; kf++) {
            wmma::fragment<wmma::matrix_a, 16, 16, 16, __half, wmma::row_major> a[2];
#pragma unroll
            for (int i = 0; i < 2; i++)
                wmma::load_matrix_sync(a[i], Asb + (warp_m * 32 + i * 16) * G_ALD + kf * 16, G_ALD);
#pragma unroll
            for (int jh = 0; jh < 2; jh++) {
                wmma::fragment<wmma::matrix_b, 16, 16, 16, __half, wmma::row_major> b[2];
#pragma unroll
                for (int jn = 0; jn < 2; jn++)
                    wmma::load_matrix_sync(b[jn],
                        Bsb + (kf * 16) * G_BLD + warp_n * 64 + (jh * 2 + jn) * 16, G_BLD);
#pragma unroll
                for (int i = 0; i < 2; i++)
#pragma unroll
                    for (int jn = 0; jn < 2; jn++)
                        wmma::mma_sync(acc[i][jh * 2 + jn], a[i], b[jn], acc[i][jh * 2 + jn]);
            }
        }
        buf = (buf + 1 >= 3) ? 0 : buf + 1;
    }
#undef GEMM_PREFETCH
    __syncthreads();

    // Epilogue
#pragma unroll
    for (int i = 0; i < 2; i++) {
#pragma unroll
        for (int j = 0; j < 4; j++) {
            wmma::store_matrix_sync(&stage[wid][0], acc[i][j], 16, wmma::mem_row_major);
            __syncwarp();
            int grow0 = m0 + warp_m * 32 + i * 16;
            int gcol0 = n0 + warp_n * 64 + j * 16;
#pragma unroll
            for (int t = lane; t < 256; t += 32) {
                int r = t >> 4, c = t & 15;
                int grow = grow0 + r;
                int gcol = gcol0 + c;
                float v = stage[wid][t] + bias[gcol];
                if (MODE == 0) {
                    int b_ = grow >> 11;
                    int qr = grow & 2047;
                    int h_ = gcol >> 6;
                    int d_ = gcol & 63;
                    if (z == 0) {
                        size_t addr = (((size_t)(b_ * NHEADS + h_) * SQ) + qr) * DHEAD + d_;
                        g_qh[addr] = __float2half(v * QSCALE);
                    } else if (z == 1) {
                        size_t addr = (((size_t)(b_ * NHEADS + h_) * SK) + qr) * DHEAD + d_;
                        g_kh[addr] = __float2half(v);
                    } else {
                        size_t addr = (((size_t)(b_ * NHEADS + h_) * DHEAD) + d_) * SK + qr;
                        g_vt[addr] = __float2half(v);            // transposed
                    }
                } else {
                    out[(size_t)grow * DMODEL + gcol] = v;
                }
            }
            __syncwarp();
        }
    }
}

// ---------------------------------------------------------------------------
// Flash attention fp16: register-resident S/O, mma.m16n8k16, TRIPLE-buffered
// K/Vt tiles with one __syncthreads per key-tile, exp2-domain softmax
// (Q pre-scaled by 0.125*log2e in the projection).
// ---------------------------------------------------------------------------
#define FLD 72                       // halves per row (64 + 8 pad)
#define FL_TSZ (64 * FLD)            // halves per tile
#define FLASH_SMEM ((6 * FL_TSZ) * (int)sizeof(__half))   // 55296

__global__ __launch_bounds__(256)
void flash_attn_kernel()
{
    extern __shared__ __half fsm[];
    __half* Ksm = fsm;                 // [3][64][FLD]; bufs 0-1 double as Q staging
    __half* Vsm = fsm + 3 * FL_TSZ;    // [3][64][FLD]

    const int q0  = blockIdx.x * 128;
    const int h   = blockIdx.y;
    const int b   = blockIdx.z;
    const int tid = threadIdx.x;
    const int wid = tid >> 5;
    const int lane = tid & 31;
    const int g = lane >> 2;
    const int q = lane & 3;

    const __half* Qg = g_qh + (((size_t)(b * NHEADS + h) * SQ) + q0) * DHEAD;
    const __half* Kg = g_kh + ((size_t)(b * NHEADS + h) * SK) * DHEAD;
    const __half* Vg = g_vt + ((size_t)(b * NHEADS + h) * DHEAD) * SK;

    // ---- Stage Q tile (128 x 64 halves) into Ksm bufs 0-1, build A frags ----
#pragma unroll
    for (int i = 0; i < 4; i++) {
        int idx = tid + i * 256;
        int r = idx >> 3, c = idx & 7;
        cp_async16(&Ksm[r * FLD + c * 8], Qg + (size_t)r * DHEAD + c * 8);
    }
    cp_commit();
    cp_wait<0>();
    __syncthreads();

    uint32_t qa[4][4];
    {
        const uint32_t* Qw = (const uint32_t*)Ksm;
        const int r0 = wid * 16 + g;
#pragma unroll
        for (int kc = 0; kc < 4; kc++) {
            qa[kc][0] = Qw[(r0)     * (FLD / 2) + kc * 8 + q];
            qa[kc][1] = Qw[(r0 + 8) * (FLD / 2) + kc * 8 + q];
            qa[kc][2] = Qw[(r0)     * (FLD / 2) + kc * 8 + q + 4];
            qa[kc][3] = Qw[(r0 + 8) * (FLD / 2) + kc * 8 + q + 4];
        }
    }
    __syncthreads();   // everyone done reading Q before K overwrites

#define FL_PREFETCH(J, BUF)                                                         \
    {                                                                               \
        _Pragma("unroll")                                                           \
        for (int i = 0; i < 2; i++) {                                               \
            int idx = tid + i * 256;                                                \
            int r = idx >> 3, c = idx & 7;                                          \
            cp_async16(&Ksm[(BUF) * FL_TSZ + r * FLD + c * 8],                      \
                       Kg + (size_t)((J) * 64 + r) * DHEAD + c * 8);                \
            cp_async16(&Vsm[(BUF) * FL_TSZ + r * FLD + c * 8],                      \
                       Vg + (size_t)r * SK + (J) * 64 + c * 8);                     \
        }                                                                           \
        cp_commit();                                                                \
    }

    FL_PREFETCH(0, 0);
    FL_PREFETCH(1, 1);

    float oacc[8][4];
#pragma unroll
    for (int nb = 0; nb < 8; nb++)
#pragma unroll
        for (int t = 0; t < 4; t++) oacc[nb][t] = 0.0f;

    float m0r = -CUDART_INF_F, m1r = -CUDART_INF_F;
    float l0r = 0.0f, l1r = 0.0f;

    const int NT = SK / 64;  // 32
    int buf = 0;
    for (int j = 0; j < NT; j++) {
        if (j + 1 < NT) cp_wait<1>(); else cp_wait<0>();
        __syncthreads();
        // prefetch into the stage retired at j-1 (fenced by the barrier above)
        if (j + 2 < NT) {
            int nbuf = (buf + 2 >= 3) ? buf - 1 : buf + 2;
            FL_PREFETCH(j + 2, nbuf);
        }

        const uint32_t* Kb = (const uint32_t*)(Ksm + buf * FL_TSZ);
        const uint32_t* Vb = (const uint32_t*)(Vsm + buf * FL_TSZ);

        // ---- S (log2-domain logits; Q pre-scaled) ----
        float sacc[8][4];
#pragma unroll
        for (int nb = 0; nb < 8; nb++) {
#pragma unroll
            for (int t = 0; t < 4; t++) sacc[nb][t] = 0.0f;
#pragma unroll
            for (int kc = 0; kc < 4; kc++) {
                uint32_t b0 = Kb[(nb * 8 + g) * (FLD / 2) + kc * 8 + q];
                uint32_t b1 = Kb[(nb * 8 + g) * (FLD / 2) + kc * 8 + q + 4];
                mma_f16(sacc[nb], qa[kc], b0, b1);
            }
        }

        // ---- online softmax (exp2 domain), rows g and g+8 ----
        float mx0 = -CUDART_INF_F, mx1 = -CUDART_INF_F;
#pragma unroll
        for (int nb = 0; nb < 8; nb++) {
            mx0 = fmaxf(mx0, fmaxf(sacc[nb][0], sacc[nb][1]));
            mx1 = fmaxf(mx1, fmaxf(sacc[nb][2], sacc[nb][3]));
        }
        mx0 = fmaxf(mx0, __shfl_xor_sync(0xffffffffu, mx0, 1));
        mx0 = fmaxf(mx0, __shfl_xor_sync(0xffffffffu, mx0, 2));
        mx1 = fmaxf(mx1, __shfl_xor_sync(0xffffffffu, mx1, 1));
        mx1 = fmaxf(mx1, __shfl_xor_sync(0xffffffffu, mx1, 2));

        float mn0 = fmaxf(m0r, mx0), mn1 = fmaxf(m1r, mx1);
        float al0 = exp2f(m0r - mn0), al1 = exp2f(m1r - mn1);
        m0r = mn0; m1r = mn1;

        float s0 = 0.0f, s1 = 0.0f;
#pragma unroll
        for (int nb = 0; nb < 8; nb++) {
            sacc[nb][0] = exp2f(sacc[nb][0] - mn0); s0 += sacc[nb][0];
            sacc[nb][1] = exp2f(sacc[nb][1] - mn0); s0 += sacc[nb][1];
            sacc[nb][2] = exp2f(sacc[nb][2] - mn1); s1 += sacc[nb][2];
            sacc[nb][3] = exp2f(sacc[nb][3] - mn1); s1 += sacc[nb][3];
        }
        s0 += __shfl_xor_sync(0xffffffffu, s0, 1);
        s0 += __shfl_xor_sync(0xffffffffu, s0, 2);
        s1 += __shfl_xor_sync(0xffffffffu, s1, 1);
        s1 += __shfl_xor_sync(0xffffffffu, s1, 2);
        l0r = l0r * al0 + s0;
        l1r = l1r * al1 + s1;

#pragma unroll
        for (int nb = 0; nb < 8; nb++) {
            oacc[nb][0] *= al0; oacc[nb][1] *= al0;
            oacc[nb][2] *= al1; oacc[nb][3] *= al1;
        }

        // ---- O += P @ Vt : P accum pairs pack directly into A frags ----
#pragma unroll
        for (int kc = 0; kc < 4; kc++) {
            uint32_t pa[4];
            pa[0] = pack_f16x2(sacc[2 * kc][1],     sacc[2 * kc][0]);
            pa[1] = pack_f16x2(sacc[2 * kc][3],     sacc[2 * kc][2]);
            pa[2] = pack_f16x2(sacc[2 * kc + 1][1], sacc[2 * kc + 1][0]);
            pa[3] = pack_f16x2(sacc[2 * kc + 1][3], sacc[2 * kc + 1][2]);
#pragma unroll
            for (int nb = 0; nb < 8; nb++) {
                uint32_t vb0 = Vb[(nb * 8 + g) * (FLD / 2) + kc * 8 + q];
                uint32_t vb1 = Vb[(nb * 8 + g) * (FLD / 2) + kc * 8 + q + 4];
                mma_f16(oacc[nb], pa, vb0, vb1);
            }
        }

        buf = (buf + 1 >= 3) ? 0 : buf + 1;
    }
#undef FL_PREFETCH

    // ---- normalize + write merged [b, q, h*64+d] as fp16 ----
    float inv0 = 1.0f / l0r, inv1 = 1.0f / l1r;
    int r0 = q0 + wid * 16 + g;
    uint32_t* og0 = (uint32_t*)(g_attn + ((size_t)(b * SQ + r0) * DMODEL) + h * DHEAD);
    uint32_t* og1 = (uint32_t*)(g_attn + ((size_t)(b * SQ + r0 + 8) * DMODEL) + h * DHEAD);
#pragma unroll
    for (int nb = 0; nb < 8; nb++) {
        og0[nb * 4 + q] = pack_f16x2(oacc[nb][1] * inv0, oacc[nb][0] * inv0);
        og1[nb * 4 + q] = pack_f16x2(oacc[nb][3] * inv1, oacc[nb][2] * inv1);
    }
}

// ---------------------------------------------------------------------------
// Launch
// ---------------------------------------------------------------------------
extern "C" void kernel_launch(void* const* d_in, const int* in_sizes, int n_in,
                              void* d_out, int out_size)
{
    const float* q  = (const float*)d_in[0];
    const float* k  = (const float*)d_in[1];
    const float* v  = (const float*)d_in[2];
    const float* Wq = (const float*)d_in[3];
    const float* bq = (const float*)d_in[4];
    const float* Wk = (const float*)d_in[5];
    const float* bk = (const float*)d_in[6];
    const float* Wv = (const float*)d_in[7];
    const float* bv = (const float*)d_in[8];
    const float* Wo = (const float*)d_in[9];
    const float* bo = (const float*)d_in[10];
    float* out = (float*)d_out;

    static bool attr_done = false;
    if (!attr_done) {
        cudaFuncSetAttribute(gemm_f16_kernel<0>, cudaFuncAttributeMaxDynamicSharedMemorySize, GEMM_SMEM);
        cudaFuncSetAttribute(gemm_f16_kernel<1>, cudaFuncAttributeMaxDynamicSharedMemorySize, GEMM_SMEM);
        cudaFuncSetAttribute(flash_attn_kernel, cudaFuncAttributeMaxDynamicSharedMemorySize, FLASH_SMEM);
        attr_done = true;
    }

    // 1. Convert inputs + weights to fp16 (one launch)
    {
        dim3 cgrid(4096, 7);
        preconvert_kernel<<<cgrid, 256>>>((const float4*)q, (const float4*)k, (const float4*)v,
                                          (const float4*)Wq, (const float4*)Wk,
                                          (const float4*)Wv, (const float4*)Wo);
    }

    // 2. Batched Q/K/V projections -> head-major fp16 scratch (V transposed)
    {
        dim3 ggrid(DMODEL / 128, MROWS / 128, 3);   // (8, 32, 3)
        gemm_f16_kernel<0><<<ggrid, 256, GEMM_SMEM>>>(bq, bk, bv, nullptr);
    }

    // 3. Flash attention
    {
        dim3 fgrid(SQ / 128, NHEADS, NBATCH);       // (16, 16, 2)
        flash_attn_kernel<<<fgrid, 256, FLASH_SMEM>>>();
    }

    // 4. Output projection
    {
        dim3 ggrid(DMODEL / 128, MROWS / 128, 1);   // (8, 32)
        gemm_f16_kernel<1><<<ggrid, 256, GEMM_SMEM>>>(bo, nullptr, nullptr, out);
    }
}